// round 1
// baseline (speedup 1.0000x reference)
#include <cuda_runtime.h>
#include <cuda_bf16.h>
#include <mma.h>

using namespace nvcuda;

// Problem dims (fixed by the dataset)
#define NPTS 8192
#define DDIM 512
#define ODIM 512

static constexpr float INV2SIG2 = 1.0f / 2048.0f;   // 1/(2*32*32)
static constexpr float EPSV = 1e-8f;

// ---------------- scratch (static __device__ globals; no allocation) ----------------
__device__ __nv_bfloat16 g_xhi[NPTS * DDIM];
__device__ __nv_bfloat16 g_xlo[NPTS * DDIM];
__device__ __nv_bfloat16 g_Whi[ODIM * DDIM];
__device__ __nv_bfloat16 g_Wlo[ODIM * DDIM];
__device__ float g_sq[NPTS];
__device__ float g_invr[NPTS];
__device__ __nv_bfloat16 g_Phi[(size_t)NPTS * NPTS];   // 128 MB
__device__ __nv_bfloat16 g_Plo[(size_t)NPTS * NPTS];   // 128 MB
__device__ float g_O[(size_t)NPTS * DDIM];             // 16 MB

// ---------------- K1a: row squared norms + hi/lo split of x ----------------
__global__ void k_prep_x(const float* __restrict__ x) {
    int row = blockIdx.x * 8 + (threadIdx.x >> 5);
    int lane = threadIdx.x & 31;
    const float* xr = x + (size_t)row * DDIM;
    float s = 0.f;
    for (int c = lane; c < DDIM; c += 32) {
        float v = xr[c];
        s += v * v;
        __nv_bfloat16 hi = __float2bfloat16(v);
        g_xhi[(size_t)row * DDIM + c] = hi;
        g_xlo[(size_t)row * DDIM + c] = __float2bfloat16(v - __bfloat162float(hi));
    }
    #pragma unroll
    for (int o = 16; o > 0; o >>= 1) s += __shfl_xor_sync(0xffffffff, s, o);
    if (lane == 0) g_sq[row] = s;
}

// ---------------- K1b: hi/lo split of W ----------------
__global__ void k_prep_w(const float* __restrict__ W) {
    int i = blockIdx.x * blockDim.x + threadIdx.x;
    if (i < ODIM * DDIM) {
        float v = W[i];
        __nv_bfloat16 hi = __float2bfloat16(v);
        g_Whi[i] = hi;
        g_Wlo[i] = __float2bfloat16(v - __bfloat162float(hi));
    }
}

// ---------------- K2: Gram tile -> exp epilogue -> P (hi/lo) ----------------
// 128x128 tile, K=512, bf16 wmma (x_hi only; error budget allows it).
// 256 threads = 8 warps, warp grid 4(M) x 2(N), warp tile 32x64.
__global__ void k_gauss() {
    __shared__ __nv_bfloat16 As[128][40];
    __shared__ __nv_bfloat16 Bs[128][40];
    __shared__ float sqi[128], sqj[128];
    __shared__ float patch[8][16][20];

    int i0 = blockIdx.y * 128;
    int j0 = blockIdx.x * 128;
    int tid = threadIdx.x;
    int warp = tid >> 5, lane = tid & 31;
    int wm = warp >> 1;   // 0..3
    int wn = warp & 1;    // 0..1

    if (tid < 128) sqi[tid] = g_sq[i0 + tid];
    else           sqj[tid - 128] = g_sq[j0 + tid - 128];

    wmma::fragment<wmma::accumulator, 16, 16, 16, float> acc[2][4];
    #pragma unroll
    for (int a = 0; a < 2; a++)
        #pragma unroll
        for (int b = 0; b < 4; b++) wmma::fill_fragment(acc[a][b], 0.f);

    for (int kt = 0; kt < DDIM; kt += 32) {
        for (int idx = tid; idx < 128 * 32; idx += 256) {
            int r = idx >> 5, c = idx & 31;
            As[r][c] = g_xhi[(size_t)(i0 + r) * DDIM + kt + c];
            Bs[r][c] = g_xhi[(size_t)(j0 + r) * DDIM + kt + c];
        }
        __syncthreads();
        #pragma unroll
        for (int kc = 0; kc < 2; kc++) {
            wmma::fragment<wmma::matrix_a, 16, 16, 16, __nv_bfloat16, wmma::row_major> af[2];
            wmma::fragment<wmma::matrix_b, 16, 16, 16, __nv_bfloat16, wmma::col_major> bf[4];
            #pragma unroll
            for (int mi = 0; mi < 2; mi++)
                wmma::load_matrix_sync(af[mi], &As[wm * 32 + mi * 16][kc * 16], 40);
            #pragma unroll
            for (int ni = 0; ni < 4; ni++)
                wmma::load_matrix_sync(bf[ni], &Bs[wn * 64 + ni * 16][kc * 16], 40);
            #pragma unroll
            for (int mi = 0; mi < 2; mi++)
                #pragma unroll
                for (int ni = 0; ni < 4; ni++)
                    wmma::mma_sync(acc[mi][ni], af[mi], bf[ni], acc[mi][ni]);
        }
        __syncthreads();
    }

    // epilogue: sqd -> exp -> split -> store P
    #pragma unroll
    for (int mi = 0; mi < 2; mi++) {
        #pragma unroll
        for (int ni = 0; ni < 4; ni++) {
            wmma::store_matrix_sync(&patch[warp][0][0], acc[mi][ni], 20, wmma::mem_row_major);
            __syncwarp();
            int rr = lane >> 1;
            int cc0 = (lane & 1) * 8;
            int gi = i0 + wm * 32 + mi * 16 + rr;
            int jbase = wn * 64 + ni * 16 + cc0;
            float si = sqi[wm * 32 + mi * 16 + rr];
            #pragma unroll
            for (int e = 0; e < 8; e++) {
                float g = patch[warp][rr][cc0 + e];
                float sqd = fmaxf(si + sqj[jbase + e] - 2.f * g, 0.f);
                float p = __expf(-sqd * INV2SIG2);
                __nv_bfloat16 hi = __float2bfloat16(p);
                size_t o = (size_t)gi * NPTS + (j0 + jbase + e);
                g_Phi[o] = hi;
                g_Plo[o] = __float2bfloat16(p - __bfloat162float(hi));
            }
            __syncwarp();
        }
    }
}

// ---------------- K2.5: deterministic row sums -> 1/(r+eps) ----------------
__global__ void k_rowsum() {
    int row = blockIdx.x;
    size_t base = (size_t)row * NPTS;
    float s = 0.f;
    for (int c = threadIdx.x; c < NPTS; c += 256)
        s += __bfloat162float(g_Phi[base + c]) + __bfloat162float(g_Plo[base + c]);
    __shared__ float red[256];
    red[threadIdx.x] = s;
    __syncthreads();
    for (int o = 128; o > 0; o >>= 1) {
        if (threadIdx.x < o) red[threadIdx.x] += red[threadIdx.x + o];
        __syncthreads();
    }
    if (threadIdx.x == 0) g_invr[row] = 1.f / (red[0] + EPSV);
}

// ---------------- K3: O = P @ x with hi/lo split (3 products) ----------------
// BM=64, BN=128, BK=32, K=8192. 8 warps 2(M) x 4(N), warp tile 32x32.
__global__ void k_pv() {
    __shared__ __nv_bfloat16 Ah[64][40], Al[64][40];
    __shared__ __nv_bfloat16 Bh[32][136], Bl[32][136];

    int i0 = blockIdx.y * 64;
    int n0 = blockIdx.x * 128;
    int tid = threadIdx.x, warp = tid >> 5;
    int wm = warp >> 2;  // 0..1
    int wn = warp & 3;   // 0..3

    wmma::fragment<wmma::accumulator, 16, 16, 16, float> acc[2][2];
    #pragma unroll
    for (int a = 0; a < 2; a++)
        #pragma unroll
        for (int b = 0; b < 2; b++) wmma::fill_fragment(acc[a][b], 0.f);

    for (int kt = 0; kt < NPTS; kt += 32) {
        for (int idx = tid; idx < 64 * 32; idx += 256) {
            int r = idx >> 5, c = idx & 31;
            size_t o = (size_t)(i0 + r) * NPTS + kt + c;
            Ah[r][c] = g_Phi[o];
            Al[r][c] = g_Plo[o];
        }
        for (int idx = tid; idx < 32 * 128; idx += 256) {
            int r = idx >> 7, c = idx & 127;
            size_t o = (size_t)(kt + r) * DDIM + n0 + c;
            Bh[r][c] = g_xhi[o];
            Bl[r][c] = g_xlo[o];
        }
        __syncthreads();
        #pragma unroll
        for (int kc = 0; kc < 2; kc++) {
            wmma::fragment<wmma::matrix_a, 16, 16, 16, __nv_bfloat16, wmma::row_major> ah[2], al[2];
            wmma::fragment<wmma::matrix_b, 16, 16, 16, __nv_bfloat16, wmma::row_major> bh[2], bl[2];
            #pragma unroll
            for (int mi = 0; mi < 2; mi++) {
                wmma::load_matrix_sync(ah[mi], &Ah[wm * 32 + mi * 16][kc * 16], 40);
                wmma::load_matrix_sync(al[mi], &Al[wm * 32 + mi * 16][kc * 16], 40);
            }
            #pragma unroll
            for (int ni = 0; ni < 2; ni++) {
                wmma::load_matrix_sync(bh[ni], &Bh[kc * 16][wn * 32 + ni * 16], 136);
                wmma::load_matrix_sync(bl[ni], &Bl[kc * 16][wn * 32 + ni * 16], 136);
            }
            #pragma unroll
            for (int mi = 0; mi < 2; mi++)
                #pragma unroll
                for (int ni = 0; ni < 2; ni++) {
                    wmma::mma_sync(acc[mi][ni], ah[mi], bh[ni], acc[mi][ni]);
                    wmma::mma_sync(acc[mi][ni], ah[mi], bl[ni], acc[mi][ni]);
                    wmma::mma_sync(acc[mi][ni], al[mi], bh[ni], acc[mi][ni]);
                }
        }
        __syncthreads();
    }
    #pragma unroll
    for (int mi = 0; mi < 2; mi++)
        #pragma unroll
        for (int ni = 0; ni < 2; ni++)
            wmma::store_matrix_sync(
                &g_O[(size_t)(i0 + wm * 32 + mi * 16) * DDIM + n0 + wn * 32 + ni * 16],
                acc[mi][ni], DDIM, wmma::mem_row_major);
}

// ---------------- K4: out = (O * invr) @ W^T + b, hi/lo split ----------------
// BM=64, BN=128, BK=32, K=512. Same warp layout as K3. B is col-major (W rows).
__global__ void k_head(const float* __restrict__ bvec, float* __restrict__ out) {
    __shared__ __nv_bfloat16 Ah[64][40], Al[64][40];
    __shared__ __nv_bfloat16 Bh[128][40], Bl[128][40];
    __shared__ float patch[8][16][20];
    __shared__ float bs[128];

    int i0 = blockIdx.y * 64;
    int n0 = blockIdx.x * 128;
    int tid = threadIdx.x, warp = tid >> 5, lane = tid & 31;
    int wm = warp >> 2;  // 0..1
    int wn = warp & 3;   // 0..3

    if (tid < 128) bs[tid] = bvec[n0 + tid];

    wmma::fragment<wmma::accumulator, 16, 16, 16, float> acc[2][2];
    #pragma unroll
    for (int a = 0; a < 2; a++)
        #pragma unroll
        for (int b = 0; b < 2; b++) wmma::fill_fragment(acc[a][b], 0.f);

    for (int kt = 0; kt < DDIM; kt += 32) {
        for (int idx = tid; idx < 64 * 32; idx += 256) {
            int r = idx >> 5, c = idx & 31;
            float v = g_O[(size_t)(i0 + r) * DDIM + kt + c] * g_invr[i0 + r];
            __nv_bfloat16 hi = __float2bfloat16(v);
            Ah[r][c] = hi;
            Al[r][c] = __float2bfloat16(v - __bfloat162float(hi));
        }
        for (int idx = tid; idx < 128 * 32; idx += 256) {
            int r = idx >> 5, c = idx & 31;
            size_t o = (size_t)(n0 + r) * DDIM + kt + c;
            Bh[r][c] = g_Whi[o];
            Bl[r][c] = g_Wlo[o];
        }
        __syncthreads();
        #pragma unroll
        for (int kc = 0; kc < 2; kc++) {
            wmma::fragment<wmma::matrix_a, 16, 16, 16, __nv_bfloat16, wmma::row_major> ah[2], al[2];
            wmma::fragment<wmma::matrix_b, 16, 16, 16, __nv_bfloat16, wmma::col_major> bh[2], bl[2];
            #pragma unroll
            for (int mi = 0; mi < 2; mi++) {
                wmma::load_matrix_sync(ah[mi], &Ah[wm * 32 + mi * 16][kc * 16], 40);
                wmma::load_matrix_sync(al[mi], &Al[wm * 32 + mi * 16][kc * 16], 40);
            }
            #pragma unroll
            for (int ni = 0; ni < 2; ni++) {
                wmma::load_matrix_sync(bh[ni], &Bh[wn * 32 + ni * 16][kc * 16], 40);
                wmma::load_matrix_sync(bl[ni], &Bl[wn * 32 + ni * 16][kc * 16], 40);
            }
            #pragma unroll
            for (int mi = 0; mi < 2; mi++)
                #pragma unroll
                for (int ni = 0; ni < 2; ni++) {
                    wmma::mma_sync(acc[mi][ni], ah[mi], bh[ni], acc[mi][ni]);
                    wmma::mma_sync(acc[mi][ni], ah[mi], bl[ni], acc[mi][ni]);
                    wmma::mma_sync(acc[mi][ni], al[mi], bh[ni], acc[mi][ni]);
                }
        }
        __syncthreads();
    }

    #pragma unroll
    for (int mi = 0; mi < 2; mi++) {
        #pragma unroll
        for (int ni = 0; ni < 2; ni++) {
            wmma::store_matrix_sync(&patch[warp][0][0], acc[mi][ni], 20, wmma::mem_row_major);
            __syncwarp();
            int rr = lane >> 1;
            int cc0 = (lane & 1) * 8;
            int gi = i0 + wm * 32 + mi * 16 + rr;
            int nb = wn * 32 + ni * 16 + cc0;
            #pragma unroll
            for (int e = 0; e < 8; e++)
                out[(size_t)gi * ODIM + n0 + nb + e] = patch[warp][rr][cc0 + e] + bs[nb + e];
            __syncwarp();
        }
    }
}

// ---------------- launch ----------------
extern "C" void kernel_launch(void* const* d_in, const int* in_sizes, int n_in,
                              void* d_out, int out_size) {
    const float* x = (const float*)d_in[0];
    const float* W = (const float*)d_in[1];
    const float* b = (const float*)d_in[2];
    float* out = (float*)d_out;

    k_prep_x<<<NPTS / 8, 256>>>(x);
    k_prep_w<<<(ODIM * DDIM + 255) / 256, 256>>>(W);
    k_gauss<<<dim3(NPTS / 128, NPTS / 128), 256>>>();
    k_rowsum<<<NPTS, 256>>>();
    k_pv<<<dim3(DDIM / 128, NPTS / 64), 256>>>();
    k_head<<<dim3(ODIM / 128, NPTS / 64), 256>>>(b, out);
}